// round 3
// baseline (speedup 1.0000x reference)
#include <cuda_runtime.h>
#include <math.h>

#define N    2048
#define HID  16
#define TPB  256
#define T    32          // logits tile edge
#define NT   (N / T)     // 64 tiles per dim

// Per-signal derived scalars, packed: [i*2+0]={t,ra,dec,mc}  [i*2+1]={f_isco,dist,psi,0}
__device__ float4 g_pre4[2 * N];
// Full logits matrix (16 MB, L2-resident). Symmetric; diagonal = -inf.
__device__ float g_logits[N * N];

__global__ void pre_kernel(const float* __restrict__ p) {
    int i = blockIdx.x * blockDim.x + threadIdx.x;
    if (i >= N) return;
    const float* pi = p + i * 15;
    float m1 = fmaf(pi[0], 95.f, 5.f);
    float m2 = fmaf(pi[1], 95.f, 5.f);
    float mc = powf(m1 * m2, 0.6f) / powf(m1 + m2, 0.2f);
    g_pre4[i * 2 + 0] = make_float4(pi[5], pi[3], pi[4], mc);
    g_pre4[i * 2 + 1] = make_float4(220.f / (m1 + m2), fmaf(pi[2], 2950.f, 50.f), pi[7], 0.f);
}

__device__ __forceinline__ float gelu_erf(float x) {
    return 0.5f * x * (1.f + erff(x * 0.70710678118654752f));
}

// ---------------------------------------------------------------------------
// Logits: 32x32 pair tiles, upper triangle of tiles, smem-transposed mirror.
// ---------------------------------------------------------------------------
__global__ __launch_bounds__(TPB) void logits_kernel(
    const float* __restrict__ iw1, const float* __restrict__ ib1,
    const float* __restrict__ ig1, const float* __restrict__ ibt1,
    const float* __restrict__ iw2, const float* __restrict__ ib2)
{
    const int tiT = blockIdx.y;   // tile row (i)
    const int tjT = blockIdx.x;   // tile col (j)
    if (tjT < tiT) return;        // upper triangle only

    __shared__ float s_w1[HID * 8];
    __shared__ float s_ipre[7][T];
    __shared__ float s_tile[T][T + 1];

    const int tid  = threadIdx.x;
    const int jcol = tid & 31;
    const int rgrp = tid >> 5;    // 0..7

    if (tid < HID * 8) s_w1[tid] = iw1[tid];
    if (tid < T) {
        int ii = tiT * T + tid;
        float4 a = g_pre4[ii * 2 + 0];
        float4 b = g_pre4[ii * 2 + 1];
        s_ipre[0][tid] = a.x; s_ipre[1][tid] = a.y; s_ipre[2][tid] = a.z;
        s_ipre[3][tid] = a.w; s_ipre[4][tid] = b.x; s_ipre[5][tid] = b.y;
        s_ipre[6][tid] = b.z;
    }

    float b1v[HID], g1v[HID], bt1v[HID], w2v[HID];
#pragma unroll
    for (int h = 0; h < HID; h++) {
        b1v[h]  = ib1[h];
        g1v[h]  = ig1[h];
        bt1v[h] = ibt1[h];
        w2v[h]  = iw2[h];
    }
    const float b2 = ib2[0];

    // j-side scalars stay in registers for the whole block
    const int j = tjT * T + jcol;
    const float4 ja = g_pre4[j * 2 + 0];
    const float4 jb = g_pre4[j * 2 + 1];
    const float tj_ = ja.x, raj = ja.y, dej = ja.z, mcj = ja.w;
    const float fij = jb.x, dij = jb.y, psj = jb.z;

    const bool diag = (tiT == tjT);
    __syncthreads();

#pragma unroll
    for (int m = 0; m < 4; m++) {
        const int r = rgrp + m * 8;          // i-row within tile
        const int i = tiT * T + r;
        if (diag && j <= i) {
            if (j == i) s_tile[r][jcol] = -INFINITY;
            continue;
        }
        const float ti  = s_ipre[0][r], rai = s_ipre[1][r], dei = s_ipre[2][r];
        const float mci = s_ipre[3][r], fii = s_ipre[4][r], dii = s_ipre[5][r];
        const float psi = s_ipre[6][r];

        float dra = fabsf(rai - raj);
        float dde = fabsf(dei - dej);
        float f0 = fabsf(ti - tj_);
        float f1 = sqrtf(fmaf(dra, dra, dde * dde));
        float f2 = __fdividef(1.f, fmaf(fabsf(mci - mcj), (1.f / 30.f), 1.f));
        float f3 = __expf(-fabsf(fii - fij) * 0.01f);
        float f4 = __fdividef(fminf(dii, dij), fmaxf(dii, dij));
        float f5 = fabsf(psi - psj);
        float f6 = dra, f7 = dde;

        float z[HID];
        float mean = 0.f;
#pragma unroll
        for (int h = 0; h < HID; h++) {
            const float* w = s_w1 + h * 8;
            float a = b1v[h];
            a = fmaf(w[0], f0, a); a = fmaf(w[1], f1, a);
            a = fmaf(w[2], f2, a); a = fmaf(w[3], f3, a);
            a = fmaf(w[4], f4, a); a = fmaf(w[5], f5, a);
            a = fmaf(w[6], f6, a); a = fmaf(w[7], f7, a);
            z[h] = a;
            mean += a;
        }
        mean *= (1.f / HID);
        float var = 0.f;
#pragma unroll
        for (int h = 0; h < HID; h++) {
            float d = z[h] - mean;
            var = fmaf(d, d, var);
        }
        float inv = rsqrtf(fmaf(var, (1.f / HID), 1e-5f));
        float lg = b2;
#pragma unroll
        for (int h = 0; h < HID; h++) {
            float xn = fmaf((z[h] - mean) * inv, g1v[h], bt1v[h]);
            lg = fmaf(w2v[h], gelu_erf(xn), lg);
        }
        s_tile[r][jcol] = lg;
        if (diag) s_tile[jcol][r] = lg;   // fill lower half of diagonal tile
    }
    __syncthreads();

    // Straight store (coalesced): covers full tile, incl. mirrored diag half
#pragma unroll
    for (int k = 0; k < 4; k++) {
        int idx = k * 256 + tid;
        int r = idx >> 5, c = idx & 31;
        g_logits[(size_t)(tiT * T + r) * N + tjT * T + c] = s_tile[r][c];
    }
    // Transposed store (coalesced via padded smem) for off-diagonal tiles
    if (!diag) {
#pragma unroll
        for (int k = 0; k < 4; k++) {
            int idx = k * 256 + tid;
            int r = idx >> 5, c = idx & 31;
            g_logits[(size_t)(tjT * T + r) * N + tiT * T + c] = s_tile[c][r];
        }
    }
}

// ---------------------------------------------------------------------------
// Row kernel: max-free softmax + weighted features + overlap net.
// ---------------------------------------------------------------------------
__global__ __launch_bounds__(TPB) void row2_kernel(
    const float* __restrict__ ow1, const float* __restrict__ ob1,
    const float* __restrict__ og1, const float* __restrict__ obt1,
    const float* __restrict__ ow2, const float* __restrict__ ob2,
    float* __restrict__ out)
{
    __shared__ float s_red[8];
    __shared__ float s_red8[8][8];
    __shared__ float s_bcast[1];
    __shared__ float s_wsum[8];
    __shared__ float s_h2[32];

    const int tid  = threadIdx.x;
    const int i    = blockIdx.x;
    const int lane = tid & 31;
    const int wid  = tid >> 5;

    const float4 ia = g_pre4[i * 2 + 0];
    const float4 ib = g_pre4[i * 2 + 1];
    const float ti = ia.x, rai = ia.y, dei = ia.z, mci = ia.w;
    const float fii = ib.x, dii = ib.y, psi = ib.z;

    // ---- load row of logits, exp (no max shift: |logit| <= ~17), sum ----
    float e[8];
    const float* rowp = g_logits + (size_t)i * N;
    float lsum = 0.f;
#pragma unroll
    for (int jj = 0; jj < 8; jj++) {
        e[jj] = __expf(rowp[(jj << 8) | tid]);   // exp(-inf)=0 kills diagonal
        lsum += e[jj];
    }
#pragma unroll
    for (int o = 16; o; o >>= 1) lsum += __shfl_xor_sync(0xFFFFFFFFu, lsum, o);
    if (lane == 0) s_red[wid] = lsum;
    __syncthreads();
    if (wid == 0) {
        float s = s_red[lane & 7];
#pragma unroll
        for (int o = 4; o; o >>= 1) s += __shfl_xor_sync(0xFFFFFFFFu, s, o);
        if (lane == 0) s_bcast[0] = 1.f / s;
    }

    // ---- unnormalized weighted features (scale by invsum after reduce) ----
    float acc0 = 0, acc1 = 0, acc2 = 0, acc3 = 0, acc4 = 0, acc5 = 0, acc6 = 0, acc7 = 0;
#pragma unroll
    for (int jj = 0; jj < 8; jj++) {
        const int j = (jj << 8) | tid;
        const float w = e[jj];
        const float4 ja = g_pre4[j * 2 + 0];
        const float4 jb = g_pre4[j * 2 + 1];
        float dra = fabsf(rai - ja.y);
        float dde = fabsf(dei - ja.z);
        acc0 = fmaf(w, fabsf(ti - ja.x), acc0);
        acc1 = fmaf(w, sqrtf(fmaf(dra, dra, dde * dde)), acc1);
        acc2 = fmaf(w, __fdividef(1.f, fmaf(fabsf(mci - ja.w), (1.f / 30.f), 1.f)), acc2);
        acc3 = fmaf(w, __expf(-fabsf(fii - jb.x) * 0.01f), acc3);
        acc4 = fmaf(w, __fdividef(fminf(dii, jb.y), fmaxf(dii, jb.y)), acc4);
        acc5 = fmaf(w, fabsf(psi - jb.z), acc5);
        acc6 = fmaf(w, dra, acc6);
        acc7 = fmaf(w, dde, acc7);
    }
    float accs[8] = {acc0, acc1, acc2, acc3, acc4, acc5, acc6, acc7};
#pragma unroll
    for (int f = 0; f < 8; f++) {
        float v = accs[f];
#pragma unroll
        for (int o = 16; o; o >>= 1) v += __shfl_xor_sync(0xFFFFFFFFu, v, o);
        if (lane == 0) s_red8[wid][f] = v;
    }
    __syncthreads();
    if (tid < 8) {
        float v = 0.f;
#pragma unroll
        for (int w = 0; w < 8; w++) v += s_red8[w][tid];
        s_wsum[tid] = v * s_bcast[0];
    }
    __syncthreads();

    // ---- overlap net: 8 -> 32 (LN + gelu) -> 16, warp 0 only ----
    if (tid < 32) {
        float a = ob1[tid];
#pragma unroll
        for (int f = 0; f < 8; f++) a = fmaf(ow1[tid * 8 + f], s_wsum[f], a);
        float s = a;
#pragma unroll
        for (int o = 16; o; o >>= 1) s += __shfl_xor_sync(0xFFFFFFFFu, s, o);
        float mu = s * (1.f / 32.f);
        float d = a - mu;
        float v = d * d;
#pragma unroll
        for (int o = 16; o; o >>= 1) v += __shfl_xor_sync(0xFFFFFFFFu, v, o);
        float invs = rsqrtf(fmaf(v, (1.f / 32.f), 1e-5f));
        float xn = fmaf(d * invs, og1[tid], obt1[tid]);
        s_h2[tid] = gelu_erf(xn);
        __syncwarp();
        if (tid < 16) {
            float o_ = ob2[tid];
#pragma unroll
            for (int k = 0; k < 32; k++) o_ = fmaf(ow2[tid * 32 + k], s_h2[k], o_);
            out[i * 16 + tid] = o_;
        }
    }
}

extern "C" void kernel_launch(void* const* d_in, const int* in_sizes, int n_in,
                              void* d_out, int out_size) {
    const float* params = (const float*)d_in[0];
    const float* iw1  = (const float*)d_in[1];
    const float* ib1  = (const float*)d_in[2];
    const float* ig1  = (const float*)d_in[3];
    const float* ibt1 = (const float*)d_in[4];
    const float* iw2  = (const float*)d_in[5];
    const float* ib2  = (const float*)d_in[6];
    const float* ow1  = (const float*)d_in[7];
    const float* ob1  = (const float*)d_in[8];
    const float* og1  = (const float*)d_in[9];
    const float* obt1 = (const float*)d_in[10];
    const float* ow2  = (const float*)d_in[11];
    const float* ob2  = (const float*)d_in[12];
    float* out = (float*)d_out;

    pre_kernel<<<(N + 255) / 256, 256>>>(params);
    dim3 lgrid(NT, NT);
    logits_kernel<<<lgrid, TPB>>>(iw1, ib1, ig1, ibt1, iw2, ib2);
    row2_kernel<<<N, TPB>>>(ow1, ob1, og1, obt1, ow2, ob2, out);
}

// round 4
// speedup vs baseline: 1.0792x; 1.0792x over previous
#include <cuda_runtime.h>
#include <math.h>

#define N    2048
#define HID  16
#define TPB  256

// Per-signal derived scalars, packed: [i*2+0]={t,ra,dec,mc}  [i*2+1]={f_isco,dist,psi,0}
__device__ float4 g_pre4[2 * N];
// exp(logit) matrix (16 MB, L2-resident). Symmetric; diagonal = 0.
__device__ float g_ew[N * N];
// Preprocessed importance-net weights:
//  g_wA[h] = W1'[h][0..3], g_wB[h] = W1'[h][4..7]  (W1' = W1 - colmean)
//  g_pp[h] = { g1[h], bt1[h], w2[h], b1'[h] }      (b1' = b1 - mean(b1))
__device__ float4 g_wA[HID], g_wB[HID], g_pp[HID];

__global__ void pre_kernel(const float* __restrict__ p,
                           const float* __restrict__ iw1, const float* __restrict__ ib1,
                           const float* __restrict__ ig1, const float* __restrict__ ibt1,
                           const float* __restrict__ iw2)
{
    __shared__ float s_col[8];
    int tid = threadIdx.x;
    int i = blockIdx.x * blockDim.x + tid;
    if (i < N) {
        const float* pi = p + i * 15;
        float m1 = fmaf(pi[0], 95.f, 5.f);
        float m2 = fmaf(pi[1], 95.f, 5.f);
        float mc = powf(m1 * m2, 0.6f) / powf(m1 + m2, 0.2f);
        g_pre4[i * 2 + 0] = make_float4(pi[5], pi[3], pi[4], mc);
        g_pre4[i * 2 + 1] = make_float4(220.f / (m1 + m2), fmaf(pi[2], 2950.f, 50.f), pi[7], 0.f);
    }
    if (blockIdx.x == 0) {
        if (tid < 8) {
            float s = 0.f;
#pragma unroll
            for (int h = 0; h < HID; h++) s += iw1[h * 8 + tid];
            s_col[tid] = s * (1.f / HID);
        }
        __syncthreads();
        if (tid < HID) {
            int h = tid;
            g_wA[h] = make_float4(iw1[h*8+0] - s_col[0], iw1[h*8+1] - s_col[1],
                                  iw1[h*8+2] - s_col[2], iw1[h*8+3] - s_col[3]);
            g_wB[h] = make_float4(iw1[h*8+4] - s_col[4], iw1[h*8+5] - s_col[5],
                                  iw1[h*8+6] - s_col[6], iw1[h*8+7] - s_col[7]);
            float bm = 0.f;
#pragma unroll
            for (int k = 0; k < HID; k++) bm += ib1[k];
            bm *= (1.f / HID);
            g_pp[h] = make_float4(ig1[h], ibt1[h], iw2[h], ib1[h] - bm);
        }
    }
}

__device__ __forceinline__ float gelu_erf(float x) {
    return 0.5f * x * (1.f + erff(x * 0.70710678118654752f));
}

// ---------------------------------------------------------------------------
// Kernel B: importance-net exp(logits), upper triangle only (j > i), mirrored.
// ---------------------------------------------------------------------------
__global__ __launch_bounds__(TPB) void logits_kernel(const float* __restrict__ ib2)
{
    __shared__ float4 s_wA[HID], s_wB[HID], s_pp[HID];

    const int tid = threadIdx.x;
    const int i   = blockIdx.x;

    if (tid < HID)            s_wA[tid]       = g_wA[tid];
    else if (tid < 2 * HID)   s_wB[tid - HID] = g_wB[tid - HID];
    else if (tid < 3 * HID)   s_pp[tid - 2*HID] = g_pp[tid - 2*HID];

    const float b2 = ib2[0];

    const float4 ia = g_pre4[i * 2 + 0];
    const float4 ibv = g_pre4[i * 2 + 1];
    const float ti = ia.x, rai = ia.y, dei = ia.z, mci = ia.w;
    const float fii = ibv.x, dii = ibv.y, psi = ibv.z;

    if (tid == 0) g_ew[(size_t)i * N + i] = 0.f;   // exp(-inf)

    __syncthreads();

    for (int j = i + 1 + tid; j < N; j += TPB) {
        const float4 ja = g_pre4[j * 2 + 0];
        const float4 jb = g_pre4[j * 2 + 1];

        float dra = fabsf(rai - ja.y);
        float dde = fabsf(dei - ja.z);
        float f0 = fabsf(ti - ja.x);
        float ss = fmaxf(fmaf(dra, dra, dde * dde), 1e-30f);
        float f1 = ss * rsqrtf(ss);
        float f2 = __fdividef(1.f, fmaf(fabsf(mci - ja.w), (1.f / 30.f), 1.f));
        float f3 = __expf(-fabsf(fii - jb.x) * 0.01f);
        float f4 = __fdividef(fminf(dii, jb.y), fmaxf(dii, jb.y));
        float f5 = fabsf(psi - jb.z);

        float zc[HID];
        float var = 0.f;
#pragma unroll
        for (int h = 0; h < HID; h++) {
            float4 wa = s_wA[h];
            float4 wb = s_wB[h];
            float a = s_pp[h].w;                 // b1'
            a = fmaf(wa.x, f0, a); a = fmaf(wa.y, f1, a);
            a = fmaf(wa.z, f2, a); a = fmaf(wa.w, f3, a);
            a = fmaf(wb.x, f4, a); a = fmaf(wb.y, f5, a);
            a = fmaf(wb.z, dra, a); a = fmaf(wb.w, dde, a);
            zc[h] = a;
            var = fmaf(a, a, var);
        }
        float inv = rsqrtf(fmaf(var, (1.f / HID), 1e-5f));
        float lg = b2;
#pragma unroll
        for (int h = 0; h < HID; h++) {
            float4 pp = s_pp[h];
            float xn = fmaf(zc[h] * inv, pp.x, pp.y);
            lg = fmaf(pp.z, gelu_erf(xn), lg);
        }
        float e = __expf(lg);
        g_ew[(size_t)i * N + j] = e;   // coalesced
        g_ew[(size_t)j * N + i] = e;   // scattered mirror (hidden under compute)
    }
}

// ---------------------------------------------------------------------------
// Kernel C: per-row sum + weighted features + overlap net.
// ---------------------------------------------------------------------------
__global__ __launch_bounds__(TPB) void row2_kernel(
    const float* __restrict__ ow1, const float* __restrict__ ob1,
    const float* __restrict__ og1, const float* __restrict__ obt1,
    const float* __restrict__ ow2, const float* __restrict__ ob2,
    float* __restrict__ out)
{
    __shared__ float s_red[8];
    __shared__ float s_red8[8][8];
    __shared__ float s_bcast[1];
    __shared__ float s_wsum[8];
    __shared__ float s_h2[32];

    const int tid  = threadIdx.x;
    const int i    = blockIdx.x;
    const int lane = tid & 31;
    const int wid  = tid >> 5;

    const float4 ia = g_pre4[i * 2 + 0];
    const float4 ibv = g_pre4[i * 2 + 1];
    const float ti = ia.x, rai = ia.y, dei = ia.z, mci = ia.w;
    const float fii = ibv.x, dii = ibv.y, psi = ibv.z;

    // ---- load row of exp(logits), sum ----
    float e[8];
    const float* rowp = g_ew + (size_t)i * N;
    float lsum = 0.f;
#pragma unroll
    for (int jj = 0; jj < 8; jj++) {
        e[jj] = rowp[(jj << 8) | tid];
        lsum += e[jj];
    }
#pragma unroll
    for (int o = 16; o; o >>= 1) lsum += __shfl_xor_sync(0xFFFFFFFFu, lsum, o);
    if (lane == 0) s_red[wid] = lsum;
    __syncthreads();
    if (wid == 0) {
        float s = s_red[lane & 7];
#pragma unroll
        for (int o = 4; o; o >>= 1) s += __shfl_xor_sync(0xFFFFFFFFu, s, o);
        if (lane == 0) s_bcast[0] = 1.f / s;
    }

    // ---- unnormalized weighted features (scale by invsum after reduce) ----
    float acc0 = 0, acc1 = 0, acc2 = 0, acc3 = 0, acc4 = 0, acc5 = 0, acc6 = 0, acc7 = 0;
#pragma unroll
    for (int jj = 0; jj < 8; jj++) {
        const int j = (jj << 8) | tid;
        const float w = e[jj];
        const float4 ja = g_pre4[j * 2 + 0];
        const float4 jb = g_pre4[j * 2 + 1];
        float dra = fabsf(rai - ja.y);
        float dde = fabsf(dei - ja.z);
        float ss = fmaxf(fmaf(dra, dra, dde * dde), 1e-30f);
        acc0 = fmaf(w, fabsf(ti - ja.x), acc0);
        acc1 = fmaf(w, ss * rsqrtf(ss), acc1);
        acc2 = fmaf(w, __fdividef(1.f, fmaf(fabsf(mci - ja.w), (1.f / 30.f), 1.f)), acc2);
        acc3 = fmaf(w, __expf(-fabsf(fii - jb.x) * 0.01f), acc3);
        acc4 = fmaf(w, __fdividef(fminf(dii, jb.y), fmaxf(dii, jb.y)), acc4);
        acc5 = fmaf(w, fabsf(psi - jb.z), acc5);
        acc6 = fmaf(w, dra, acc6);
        acc7 = fmaf(w, dde, acc7);
    }
    float accs[8] = {acc0, acc1, acc2, acc3, acc4, acc5, acc6, acc7};
#pragma unroll
    for (int f = 0; f < 8; f++) {
        float v = accs[f];
#pragma unroll
        for (int o = 16; o; o >>= 1) v += __shfl_xor_sync(0xFFFFFFFFu, v, o);
        if (lane == 0) s_red8[wid][f] = v;
    }
    __syncthreads();
    if (tid < 8) {
        float v = 0.f;
#pragma unroll
        for (int w = 0; w < 8; w++) v += s_red8[w][tid];
        s_wsum[tid] = v * s_bcast[0];
    }
    __syncthreads();

    // ---- overlap net: 8 -> 32 (LN + gelu) -> 16, warp 0 only ----
    if (tid < 32) {
        float a = ob1[tid];
#pragma unroll
        for (int f = 0; f < 8; f++) a = fmaf(ow1[tid * 8 + f], s_wsum[f], a);
        float s = a;
#pragma unroll
        for (int o = 16; o; o >>= 1) s += __shfl_xor_sync(0xFFFFFFFFu, s, o);
        float mu = s * (1.f / 32.f);
        float d = a - mu;
        float v = d * d;
#pragma unroll
        for (int o = 16; o; o >>= 1) v += __shfl_xor_sync(0xFFFFFFFFu, v, o);
        float invs = rsqrtf(fmaf(v, (1.f / 32.f), 1e-5f));
        float xn = fmaf(d * invs, og1[tid], obt1[tid]);
        s_h2[tid] = gelu_erf(xn);
        __syncwarp();
        if (tid < 16) {
            float o_ = ob2[tid];
#pragma unroll
            for (int k = 0; k < 32; k++) o_ = fmaf(ow2[tid * 32 + k], s_h2[k], o_);
            out[i * 16 + tid] = o_;
        }
    }
}

extern "C" void kernel_launch(void* const* d_in, const int* in_sizes, int n_in,
                              void* d_out, int out_size) {
    const float* params = (const float*)d_in[0];
    const float* iw1  = (const float*)d_in[1];
    const float* ib1  = (const float*)d_in[2];
    const float* ig1  = (const float*)d_in[3];
    const float* ibt1 = (const float*)d_in[4];
    const float* iw2  = (const float*)d_in[5];
    const float* ib2  = (const float*)d_in[6];
    const float* ow1  = (const float*)d_in[7];
    const float* ob1  = (const float*)d_in[8];
    const float* og1  = (const float*)d_in[9];
    const float* obt1 = (const float*)d_in[10];
    const float* ow2  = (const float*)d_in[11];
    const float* ob2  = (const float*)d_in[12];
    float* out = (float*)d_out;

    pre_kernel<<<(N + 255) / 256, 256>>>(params, iw1, ib1, ig1, ibt1, iw2);
    logits_kernel<<<N, TPB>>>(ib2);
    row2_kernel<<<N, TPB>>>(ow1, ob1, og1, obt1, ow2, ob2, out);
}

// round 5
// speedup vs baseline: 1.1837x; 1.0968x over previous
#include <cuda_runtime.h>
#include <math.h>

#define N    2048
#define HID  16
#define TPB  256

// Per-signal derived scalars, packed: [i*2+0]={t,ra,dec,mc}  [i*2+1]={f_isco,dist,psi,0}
__device__ float4 g_pre4[2 * N];
// exp(logit) matrix (16 MB, L2-resident). Symmetric; diagonal = 0.
__device__ float g_ew[N * N];
// Preprocessed importance-net weights:
//  g_wA[h] = W1'[h][0..3], g_wB[h] = W1'[h][4..7]  (W1' = W1 - colmean)
//  g_pp[h] = { g1[h], bt1[h], w2[h], b1'[h] }      (b1' = b1 - mean(b1))
__device__ float4 g_wA[HID], g_wB[HID], g_pp[HID];

__global__ void pre_kernel(const float* __restrict__ p,
                           const float* __restrict__ iw1, const float* __restrict__ ib1,
                           const float* __restrict__ ig1, const float* __restrict__ ibt1,
                           const float* __restrict__ iw2)
{
    __shared__ float s_col[8];
    int tid = threadIdx.x;
    int i = blockIdx.x * blockDim.x + tid;
    if (i < N) {
        const float* pi = p + i * 15;
        float m1 = fmaf(pi[0], 95.f, 5.f);
        float m2 = fmaf(pi[1], 95.f, 5.f);
        // __powf: log2/exp2 based, rel err ~1e-6 — feeds only the smooth mass-sim feature
        float mc = __powf(m1 * m2, 0.6f) * __powf(m1 + m2, -0.2f);
        g_pre4[i * 2 + 0] = make_float4(pi[5], pi[3], pi[4], mc);
        g_pre4[i * 2 + 1] = make_float4(220.f / (m1 + m2), fmaf(pi[2], 2950.f, 50.f), pi[7], 0.f);
    }
    if (blockIdx.x == 0) {
        if (tid < 8) {
            float s = 0.f;
#pragma unroll
            for (int h = 0; h < HID; h++) s += iw1[h * 8 + tid];
            s_col[tid] = s * (1.f / HID);
        }
        __syncthreads();
        if (tid < HID) {
            int h = tid;
            g_wA[h] = make_float4(iw1[h*8+0] - s_col[0], iw1[h*8+1] - s_col[1],
                                  iw1[h*8+2] - s_col[2], iw1[h*8+3] - s_col[3]);
            g_wB[h] = make_float4(iw1[h*8+4] - s_col[4], iw1[h*8+5] - s_col[5],
                                  iw1[h*8+6] - s_col[6], iw1[h*8+7] - s_col[7]);
            float bm = 0.f;
#pragma unroll
            for (int k = 0; k < HID; k++) bm += ib1[k];
            bm *= (1.f / HID);
            g_pp[h] = make_float4(ig1[h], ibt1[h], iw2[h], ib1[h] - bm);
        }
    }
}

// Fast erf-GELU: Abramowitz-Stegun 7.1.26, max abs err ~1.5e-7.
__device__ __forceinline__ float gelu_fast(float x) {
    float ax = fabsf(x) * 0.70710678118654752f;       // |x|/sqrt(2)
    float u  = __fdividef(1.f, fmaf(0.3275911f, ax, 1.f));
    float pl = fmaf(fmaf(fmaf(fmaf(1.061405429f, u, -1.453152027f),
                               u, 1.421413741f),
                          u, -0.284496736f),
                     u, 0.254829592f) * u;
    float e  = __expf(-ax * ax);
    float er = fmaf(-pl, e, 1.f);                      // erf(|x|/sqrt2)
    er = copysignf(er, x);
    return 0.5f * x * (1.f + er);
}

// ---------------------------------------------------------------------------
// Kernel B: importance-net exp(logits), upper triangle only (j > i), mirrored.
// ---------------------------------------------------------------------------
__global__ __launch_bounds__(TPB) void logits_kernel(const float* __restrict__ ib2)
{
    __shared__ float4 s_wA[HID], s_wB[HID], s_pp[HID];

    const int tid = threadIdx.x;
    const int i   = blockIdx.x;

    if (tid < HID)            s_wA[tid]         = g_wA[tid];
    else if (tid < 2 * HID)   s_wB[tid - HID]   = g_wB[tid - HID];
    else if (tid < 3 * HID)   s_pp[tid - 2*HID] = g_pp[tid - 2*HID];

    const float b2 = ib2[0];

    const float4 ia  = g_pre4[i * 2 + 0];
    const float4 ibv = g_pre4[i * 2 + 1];
    const float ti = ia.x, rai = ia.y, dei = ia.z, mci = ia.w;
    const float fii = ibv.x, dii = ibv.y, psi = ibv.z;

    if (tid == 0) g_ew[(size_t)i * N + i] = 0.f;   // exp(-inf)

    __syncthreads();

    for (int j = i + 1 + tid; j < N; j += TPB) {
        const float4 ja = g_pre4[j * 2 + 0];
        const float4 jb = g_pre4[j * 2 + 1];

        float dra = fabsf(rai - ja.y);
        float dde = fabsf(dei - ja.z);
        float f0 = fabsf(ti - ja.x);
        float ss = fmaxf(fmaf(dra, dra, dde * dde), 1e-30f);
        float f1 = ss * rsqrtf(ss);
        float f2 = __fdividef(1.f, fmaf(fabsf(mci - ja.w), (1.f / 30.f), 1.f));
        float f3 = __expf(-fabsf(fii - jb.x) * 0.01f);
        float f4 = __fdividef(fminf(dii, jb.y), fmaxf(dii, jb.y));
        float f5 = fabsf(psi - jb.z);

        float zc[HID];
        float var = 0.f;
#pragma unroll
        for (int h = 0; h < HID; h++) {
            float4 wa = s_wA[h];
            float4 wb = s_wB[h];
            float a = s_pp[h].w;                 // b1'
            a = fmaf(wa.x, f0, a); a = fmaf(wa.y, f1, a);
            a = fmaf(wa.z, f2, a); a = fmaf(wa.w, f3, a);
            a = fmaf(wb.x, f4, a); a = fmaf(wb.y, f5, a);
            a = fmaf(wb.z, dra, a); a = fmaf(wb.w, dde, a);
            zc[h] = a;
            var = fmaf(a, a, var);
        }
        float inv = rsqrtf(fmaf(var, (1.f / HID), 1e-5f));
        float lg = b2;
#pragma unroll
        for (int h = 0; h < HID; h++) {
            float4 pp = s_pp[h];
            float xn = fmaf(zc[h] * inv, pp.x, pp.y);
            lg = fmaf(pp.z, gelu_fast(xn), lg);
        }
        float e = __expf(lg);
        g_ew[(size_t)i * N + j] = e;   // coalesced
        g_ew[(size_t)j * N + i] = e;   // scattered mirror (hidden under compute)
    }
}

// ---------------------------------------------------------------------------
// Kernel C: per-row sum + weighted features + overlap net.
// ---------------------------------------------------------------------------
__global__ __launch_bounds__(TPB) void row2_kernel(
    const float* __restrict__ ow1, const float* __restrict__ ob1,
    const float* __restrict__ og1, const float* __restrict__ obt1,
    const float* __restrict__ ow2, const float* __restrict__ ob2,
    float* __restrict__ out)
{
    __shared__ float s_red[8];
    __shared__ float s_red8[8][8];
    __shared__ float s_bcast[1];
    __shared__ float s_wsum[8];
    __shared__ float s_h2[32];

    const int tid  = threadIdx.x;
    const int i    = blockIdx.x;
    const int lane = tid & 31;
    const int wid  = tid >> 5;

    const float4 ia  = g_pre4[i * 2 + 0];
    const float4 ibv = g_pre4[i * 2 + 1];
    const float ti = ia.x, rai = ia.y, dei = ia.z, mci = ia.w;
    const float fii = ibv.x, dii = ibv.y, psi = ibv.z;

    // ---- load row of exp(logits), sum ----
    float e[8];
    const float* rowp = g_ew + (size_t)i * N;
    float lsum = 0.f;
#pragma unroll
    for (int jj = 0; jj < 8; jj++) {
        e[jj] = rowp[(jj << 8) | tid];
        lsum += e[jj];
    }
#pragma unroll
    for (int o = 16; o; o >>= 1) lsum += __shfl_xor_sync(0xFFFFFFFFu, lsum, o);
    if (lane == 0) s_red[wid] = lsum;
    __syncthreads();
    if (wid == 0) {
        float s = s_red[lane & 7];
#pragma unroll
        for (int o = 4; o; o >>= 1) s += __shfl_xor_sync(0xFFFFFFFFu, s, o);
        if (lane == 0) s_bcast[0] = 1.f / s;
    }

    // ---- unnormalized weighted features (scale by invsum after reduce) ----
    float acc0 = 0, acc1 = 0, acc2 = 0, acc3 = 0, acc4 = 0, acc5 = 0, acc6 = 0, acc7 = 0;
#pragma unroll
    for (int jj = 0; jj < 8; jj++) {
        const int j = (jj << 8) | tid;
        const float w = e[jj];
        const float4 ja = g_pre4[j * 2 + 0];
        const float4 jb = g_pre4[j * 2 + 1];
        float dra = fabsf(rai - ja.y);
        float dde = fabsf(dei - ja.z);
        float ss = fmaxf(fmaf(dra, dra, dde * dde), 1e-30f);
        acc0 = fmaf(w, fabsf(ti - ja.x), acc0);
        acc1 = fmaf(w, ss * rsqrtf(ss), acc1);
        acc2 = fmaf(w, __fdividef(1.f, fmaf(fabsf(mci - ja.w), (1.f / 30.f), 1.f)), acc2);
        acc3 = fmaf(w, __expf(-fabsf(fii - jb.x) * 0.01f), acc3);
        acc4 = fmaf(w, __fdividef(fminf(dii, jb.y), fmaxf(dii, jb.y)), acc4);
        acc5 = fmaf(w, fabsf(psi - jb.z), acc5);
        acc6 = fmaf(w, dra, acc6);
        acc7 = fmaf(w, dde, acc7);
    }
    float accs[8] = {acc0, acc1, acc2, acc3, acc4, acc5, acc6, acc7};
#pragma unroll
    for (int f = 0; f < 8; f++) {
        float v = accs[f];
#pragma unroll
        for (int o = 16; o; o >>= 1) v += __shfl_xor_sync(0xFFFFFFFFu, v, o);
        if (lane == 0) s_red8[wid][f] = v;
    }
    __syncthreads();
    if (tid < 8) {
        float v = 0.f;
#pragma unroll
        for (int w = 0; w < 8; w++) v += s_red8[w][tid];
        s_wsum[tid] = v * s_bcast[0];
    }
    __syncthreads();

    // ---- overlap net: 8 -> 32 (LN + gelu) -> 16, warp 0 only ----
    if (tid < 32) {
        float a = ob1[tid];
#pragma unroll
        for (int f = 0; f < 8; f++) a = fmaf(ow1[tid * 8 + f], s_wsum[f], a);
        float s = a;
#pragma unroll
        for (int o = 16; o; o >>= 1) s += __shfl_xor_sync(0xFFFFFFFFu, s, o);
        float mu = s * (1.f / 32.f);
        float d = a - mu;
        float v = d * d;
#pragma unroll
        for (int o = 16; o; o >>= 1) v += __shfl_xor_sync(0xFFFFFFFFu, v, o);
        float invs = rsqrtf(fmaf(v, (1.f / 32.f), 1e-5f));
        float xn = fmaf(d * invs, og1[tid], obt1[tid]);
        s_h2[tid] = gelu_fast(xn);
        __syncwarp();
        if (tid < 16) {
            float o_ = ob2[tid];
#pragma unroll
            for (int k = 0; k < 32; k++) o_ = fmaf(ow2[tid * 32 + k], s_h2[k], o_);
            out[i * 16 + tid] = o_;
        }
    }
}

extern "C" void kernel_launch(void* const* d_in, const int* in_sizes, int n_in,
                              void* d_out, int out_size) {
    const float* params = (const float*)d_in[0];
    const float* iw1  = (const float*)d_in[1];
    const float* ib1  = (const float*)d_in[2];
    const float* ig1  = (const float*)d_in[3];
    const float* ibt1 = (const float*)d_in[4];
    const float* iw2  = (const float*)d_in[5];
    const float* ib2  = (const float*)d_in[6];
    const float* ow1  = (const float*)d_in[7];
    const float* ob1  = (const float*)d_in[8];
    const float* og1  = (const float*)d_in[9];
    const float* obt1 = (const float*)d_in[10];
    const float* ow2  = (const float*)d_in[11];
    const float* ob2  = (const float*)d_in[12];
    float* out = (float*)d_out;

    pre_kernel<<<(N + 255) / 256, 256>>>(params, iw1, ib1, ig1, ibt1, iw2);
    logits_kernel<<<N, TPB>>>(ib2);
    row2_kernel<<<N, TPB>>>(ow1, ob1, og1, obt1, ow2, ob2, out);
}